// round 1
// baseline (speedup 1.0000x reference)
#include <cuda_runtime.h>
#include <math.h>

// ---------------------------------------------------------------------------
// Problem dims (fixed by the reference)
// ---------------------------------------------------------------------------
#define BN_      200
#define S_       128
#define D_       1024
#define DI_      2048
#define DS_      32
#define DCONV_   4
#define NROWS_   (BN_ * S_)          // 25600
#define XPROJ_N_ (2 * DS_ + 1)       // 65

// ---------------------------------------------------------------------------
// Scratch (device globals — no runtime allocation allowed)
// ---------------------------------------------------------------------------
__device__ float g_xn   [NROWS_ * D_];          // layernorm output        104.8 MB
__device__ float g_xz   [NROWS_ * 2 * DI_];     // in_proj output          419.4 MB
__device__ float g_xact [NROWS_ * DI_];         // conv+silu output        209.7 MB
__device__ float g_xssm [NROWS_ * XPROJ_N_];    // x_proj output             6.6 MB
__device__ float g_gate [NROWS_ * DI_];         // y * silu(z)             209.7 MB

// ---------------------------------------------------------------------------
// Helpers
// ---------------------------------------------------------------------------
__device__ __forceinline__ float siluf(float x) {
    return x / (1.0f + expf(-x));
}
__device__ __forceinline__ float softplusf(float x) {
    // numerically stable: max(x,0) + log1p(exp(-|x|))
    return fmaxf(x, 0.0f) + log1pf(expf(-fabsf(x)));
}

// ---------------------------------------------------------------------------
// 1) LayerNorm: rows of 1024, one block per row, 256 threads (4 elems each)
// ---------------------------------------------------------------------------
__global__ __launch_bounds__(256)
void ln_kernel(const float* __restrict__ x, const float* __restrict__ w,
               const float* __restrict__ b, float* __restrict__ out)
{
    __shared__ float red_s[8], red_q[8];
    const int row = blockIdx.x;
    const float* xr = x + (size_t)row * D_;
    const int c = threadIdx.x * 4;

    float4 v = *(const float4*)(xr + c);
    float s  = v.x + v.y + v.z + v.w;
    float q  = v.x * v.x + v.y * v.y + v.z * v.z + v.w * v.w;
    #pragma unroll
    for (int o = 16; o > 0; o >>= 1) {
        s += __shfl_xor_sync(0xffffffffu, s, o);
        q += __shfl_xor_sync(0xffffffffu, q, o);
    }
    const int warp = threadIdx.x >> 5;
    if ((threadIdx.x & 31) == 0) { red_s[warp] = s; red_q[warp] = q; }
    __syncthreads();
    s = 0.f; q = 0.f;
    #pragma unroll
    for (int i = 0; i < 8; i++) { s += red_s[i]; q += red_q[i]; }

    const float inv = 1.0f / (float)D_;
    const float mu  = s * inv;
    const float var = q * inv - mu * mu;
    const float rs  = rsqrtf(var + 1e-5f);

    float4 wv = *(const float4*)(w + c);
    float4 bv = *(const float4*)(b + c);
    float4 o;
    o.x = (v.x - mu) * rs * wv.x + bv.x;
    o.y = (v.y - mu) * rs * wv.y + bv.y;
    o.z = (v.z - mu) * rs * wv.z + bv.z;
    o.w = (v.w - mu) * rs * wv.w + bv.w;
    *(float4*)(out + (size_t)row * D_ + c) = o;
}

// ---------------------------------------------------------------------------
// 2) Tiled fp32 GEMM (NT form): C[m,n] = sum_k A[m,k] * B[n,k]  (+ Cadd[m,n])
//    128x128 block tile, 8x8 per thread, K-step 16, 256 threads.
//    M, N, K all multiples of the tile dims in this problem — no bounds checks.
// ---------------------------------------------------------------------------
__global__ __launch_bounds__(256, 2)
void gemm_nt_kernel(const float* __restrict__ A, const float* __restrict__ B,
                    const float* __restrict__ Cadd, float* __restrict__ C,
                    int M, int N, int K)
{
    __shared__ float As[16][128];
    __shared__ float Bs[16][128];

    const int tid = threadIdx.x;
    const int m0 = blockIdx.y * 128;
    const int n0 = blockIdx.x * 128;
    const int tx = tid & 15;          // col group (8 cols)
    const int ty = tid >> 4;          // row group (8 rows)

    // loader mapping: each thread loads one row's 8 contiguous K values (2 float4)
    const int lr = tid >> 1;          // 0..127 : row within tile
    const int lc = (tid & 1) * 8;     // 0 or 8 : k-offset within 16

    const float* Ab = A + (size_t)(m0 + lr) * K + lc;
    const float* Bb = B + (size_t)(n0 + lr) * K + lc;

    float acc[8][8];
    #pragma unroll
    for (int i = 0; i < 8; i++)
        #pragma unroll
        for (int j = 0; j < 8; j++) acc[i][j] = 0.f;

    for (int k0 = 0; k0 < K; k0 += 16) {
        float4 a0 = *(const float4*)(Ab + k0);
        float4 a1 = *(const float4*)(Ab + k0 + 4);
        float4 b0 = *(const float4*)(Bb + k0);
        float4 b1 = *(const float4*)(Bb + k0 + 4);
        __syncthreads();
        As[lc + 0][lr] = a0.x; As[lc + 1][lr] = a0.y;
        As[lc + 2][lr] = a0.z; As[lc + 3][lr] = a0.w;
        As[lc + 4][lr] = a1.x; As[lc + 5][lr] = a1.y;
        As[lc + 6][lr] = a1.z; As[lc + 7][lr] = a1.w;
        Bs[lc + 0][lr] = b0.x; Bs[lc + 1][lr] = b0.y;
        Bs[lc + 2][lr] = b0.z; Bs[lc + 3][lr] = b0.w;
        Bs[lc + 4][lr] = b1.x; Bs[lc + 5][lr] = b1.y;
        Bs[lc + 6][lr] = b1.z; Bs[lc + 7][lr] = b1.w;
        __syncthreads();

        #pragma unroll
        for (int k = 0; k < 16; k++) {
            float4 av0 = *(const float4*)&As[k][ty * 8];
            float4 av1 = *(const float4*)&As[k][ty * 8 + 4];
            float4 bv0 = *(const float4*)&Bs[k][tx * 8];
            float4 bv1 = *(const float4*)&Bs[k][tx * 8 + 4];
            float a[8] = {av0.x, av0.y, av0.z, av0.w, av1.x, av1.y, av1.z, av1.w};
            float bb[8] = {bv0.x, bv0.y, bv0.z, bv0.w, bv1.x, bv1.y, bv1.z, bv1.w};
            #pragma unroll
            for (int i = 0; i < 8; i++)
                #pragma unroll
                for (int j = 0; j < 8; j++)
                    acc[i][j] += a[i] * bb[j];
        }
    }

    // epilogue
    #pragma unroll
    for (int i = 0; i < 8; i++) {
        const size_t rowo = (size_t)(m0 + ty * 8 + i) * N + n0 + tx * 8;
        if (Cadd) {
            float4 c0 = *(const float4*)(Cadd + rowo);
            float4 c1 = *(const float4*)(Cadd + rowo + 4);
            acc[i][0] += c0.x; acc[i][1] += c0.y; acc[i][2] += c0.z; acc[i][3] += c0.w;
            acc[i][4] += c1.x; acc[i][5] += c1.y; acc[i][6] += c1.z; acc[i][7] += c1.w;
        }
        float4 o0 = make_float4(acc[i][0], acc[i][1], acc[i][2], acc[i][3]);
        float4 o1 = make_float4(acc[i][4], acc[i][5], acc[i][6], acc[i][7]);
        *(float4*)(C + rowo)     = o0;
        *(float4*)(C + rowo + 4) = o1;
    }
}

// ---------------------------------------------------------------------------
// 3) Causal depthwise conv (d_conv=4) along S + bias + SiLU.
//    One thread per (b, d); sequential over S with a register shift window.
// ---------------------------------------------------------------------------
__global__ __launch_bounds__(256)
void conv_silu_kernel(const float* __restrict__ xz, const float* __restrict__ cw,
                      const float* __restrict__ cb, float* __restrict__ xact)
{
    const int idx = blockIdx.x * 256 + threadIdx.x;   // 0 .. BN*DI-1
    const int b = idx / DI_;
    const int d = idx - b * DI_;

    const float w0 = cw[d * 4 + 0];
    const float w1 = cw[d * 4 + 1];
    const float w2 = cw[d * 4 + 2];
    const float w3 = cw[d * 4 + 3];
    const float bias = cb[d];

    const float* xin = xz + (size_t)b * S_ * (2 * DI_) + d;   // stride 4096 per s
    float* out = xact + (size_t)b * S_ * DI_ + d;             // stride 2048 per s

    float h0 = 0.f, h1 = 0.f, h2 = 0.f;
    #pragma unroll 4
    for (int s = 0; s < S_; s++) {
        float h3 = xin[(size_t)s * (2 * DI_)];
        float v = bias + w0 * h0 + w1 * h1 + w2 * h2 + w3 * h3;
        out[(size_t)s * DI_] = siluf(v);
        h0 = h1; h1 = h2; h2 = h3;
    }
}

// ---------------------------------------------------------------------------
// 4) x_proj skinny GEMM: [NROWS, 2048] @ [65, 2048]^T -> [NROWS, 65]
//    32 rows per block, K-tile 64, 256 threads (r = tid%32, cg = tid/32).
// ---------------------------------------------------------------------------
__global__ __launch_bounds__(256)
void xproj_kernel(const float* __restrict__ A, const float* __restrict__ W,
                  float* __restrict__ out)
{
    __shared__ float As[32][65];   // pad to 65 -> conflict free
    __shared__ float Ws[65][64];

    const int tid = threadIdx.x;
    const int m0 = blockIdx.x * 32;
    const int r  = tid & 31;
    const int cg = tid >> 5;       // 0..7

    float acc[9];
    #pragma unroll
    for (int j = 0; j < 9; j++) acc[j] = 0.f;

    for (int kt = 0; kt < DI_; kt += 64) {
        __syncthreads();
        // A tile: 32 rows x 64 = 512 float4
        for (int i = tid; i < 32 * 16; i += 256) {
            int rr = i >> 4, c4 = (i & 15) * 4;
            float4 v = *(const float4*)(A + (size_t)(m0 + rr) * DI_ + kt + c4);
            As[rr][c4 + 0] = v.x; As[rr][c4 + 1] = v.y;
            As[rr][c4 + 2] = v.z; As[rr][c4 + 3] = v.w;
        }
        // W tile: 65 rows x 64 = 1040 float4
        for (int i = tid; i < 65 * 16; i += 256) {
            int rr = i >> 4, c4 = (i & 15) * 4;
            float4 v = *(const float4*)(W + (size_t)rr * DI_ + kt + c4);
            Ws[rr][c4 + 0] = v.x; Ws[rr][c4 + 1] = v.y;
            Ws[rr][c4 + 2] = v.z; Ws[rr][c4 + 3] = v.w;
        }
        __syncthreads();

        #pragma unroll 16
        for (int k = 0; k < 64; k++) {
            float a = As[r][k];
            #pragma unroll
            for (int j = 0; j < 9; j++) {
                int c = cg + 8 * j;
                if (c < XPROJ_N_) acc[j] += a * Ws[c][k];
            }
        }
    }

    #pragma unroll
    for (int j = 0; j < 9; j++) {
        int c = cg + 8 * j;
        if (c < XPROJ_N_) out[(size_t)(m0 + r) * XPROJ_N_ + c] = acc[j];
    }
}

// ---------------------------------------------------------------------------
// 5) SSM scan + gating. One block per (b, 256-chunk of d). h[32] in registers.
//    B/C/delta_raw for the whole sequence staged in shared memory.
// ---------------------------------------------------------------------------
__global__ __launch_bounds__(256)
void scan_kernel(const float* __restrict__ xssm, const float* __restrict__ xact,
                 const float* __restrict__ xz,   const float* __restrict__ dtW,
                 const float* __restrict__ dtb,  const float* __restrict__ eb,
                 const float* __restrict__ es_p, float* __restrict__ gated)
{
    __shared__ float Bc[S_][DS_];
    __shared__ float Cc[S_][DS_];
    __shared__ float dr[S_];
    __shared__ float ebs[S_];

    const int b = blockIdx.x;
    const int d = blockIdx.y * 256 + threadIdx.x;
    const float es = *es_p;

    // cooperative load of x_ssm rows for this b: 128 * 65 floats
    {
        const float* src = xssm + (size_t)b * S_ * XPROJ_N_;
        for (int i = threadIdx.x; i < S_ * XPROJ_N_; i += 256) {
            int s = i / XPROJ_N_;
            int c = i - s * XPROJ_N_;
            float v = src[i];
            if (c == 0)              dr[s]          = v;
            else if (c <= DS_)       Bc[s][c - 1]   = v;
            else                     Cc[s][c - 1 - DS_] = v;
        }
        for (int i = threadIdx.x; i < S_; i += 256)
            ebs[i] = eb[(size_t)b * S_ + i];
    }
    __syncthreads();

    const float dw = dtW[d];
    const float db = dtb[d];
    const float* xa_p = xact + (size_t)b * S_ * DI_ + d;
    const float* z_p  = xz   + (size_t)b * S_ * (2 * DI_) + DI_ + d;
    float* out_p      = gated + (size_t)b * S_ * DI_ + d;

    float h[DS_];
    #pragma unroll
    for (int n = 0; n < DS_; n++) h[n] = 0.f;

    for (int s = 0; s < S_; s++) {
        const float xa = xa_p[(size_t)s * DI_];
        const float zz = z_p[(size_t)s * (2 * DI_)];
        float delta = softplusf(dr[s] * dw + db);
        delta = fmaxf(delta + es * ebs[s], 1e-4f);
        const float e = expf(-delta);
        float y = 0.f;
        #pragma unroll
        for (int n = 0; n < DS_; n++) {
            float hn = h[n] * e + Bc[s][n] * xa;
            hn = fminf(fmaxf(hn, -100.0f), 100.0f);
            h[n] = hn;
            y += hn * Cc[s][n];
        }
        out_p[(size_t)s * DI_] = y * siluf(zz);
    }
}

// ---------------------------------------------------------------------------
// launch
// ---------------------------------------------------------------------------
extern "C" void kernel_launch(void* const* d_in, const int* in_sizes, int n_in,
                              void* d_out, int out_size)
{
    const float* x      = (const float*)d_in[0];   // [BN,S,D]
    const float* eb     = (const float*)d_in[1];   // [BN,S,1]
    const float* norm_w = (const float*)d_in[2];   // [D]
    const float* norm_b = (const float*)d_in[3];   // [D]
    const float* inW    = (const float*)d_in[4];   // [4096,1024]
    const float* convw  = (const float*)d_in[5];   // [2048,1,4]
    const float* convb  = (const float*)d_in[6];   // [2048]
    const float* xpW    = (const float*)d_in[7];   // [65,2048]
    const float* dtW    = (const float*)d_in[8];   // [2048,1]
    const float* dtb    = (const float*)d_in[9];   // [2048]
    const float* outW   = (const float*)d_in[10];  // [1024,2048]
    const float* es     = (const float*)d_in[11];  // scalar

    float* out = (float*)d_out;

    float *xn, *xz, *xact, *xssm, *gate;
    cudaGetSymbolAddress((void**)&xn,   g_xn);
    cudaGetSymbolAddress((void**)&xz,   g_xz);
    cudaGetSymbolAddress((void**)&xact, g_xact);
    cudaGetSymbolAddress((void**)&xssm, g_xssm);
    cudaGetSymbolAddress((void**)&gate, g_gate);

    // 1) LayerNorm
    ln_kernel<<<NROWS_, 256>>>(x, norm_w, norm_b, xn);

    // 2) in_proj GEMM: [25600,1024] x [4096,1024]^T -> [25600,4096]
    {
        dim3 grid(2 * DI_ / 128, NROWS_ / 128);
        gemm_nt_kernel<<<grid, 256>>>(xn, inW, nullptr, xz, NROWS_, 2 * DI_, D_);
    }

    // 3) causal depthwise conv + SiLU
    conv_silu_kernel<<<(BN_ * DI_) / 256, 256>>>(xz, convw, convb, xact);

    // 4) x_proj skinny GEMM -> [25600, 65]
    xproj_kernel<<<NROWS_ / 32, 256>>>(xact, xpW, xssm);

    // 5) SSM scan + gating -> gate = y * silu(z)
    {
        dim3 grid(BN_, DI_ / 256);
        scan_kernel<<<grid, 256>>>(xssm, xact, xz, dtW, dtb, eb, es, gate);
    }

    // 6) out GEMM + residual: [25600,2048] x [1024,2048]^T + x -> d_out
    {
        dim3 grid(D_ / 128, NROWS_ / 128);
        gemm_nt_kernel<<<grid, 256>>>(gate, outW, x, out, NROWS_, D_, DI_);
    }
}

// round 3
// speedup vs baseline: 2.3934x; 2.3934x over previous
#include <cuda_runtime.h>
#include <math.h>
#include <cstdint>

// ---------------------------------------------------------------------------
// Problem dims
// ---------------------------------------------------------------------------
#define BN_      200
#define S_       128
#define D_       1024
#define DI_      2048
#define DS_      32
#define NROWS_   (BN_ * S_)          // 25600
#define XPROJ_N_ (2 * DS_ + 1)       // 65

// ---------------------------------------------------------------------------
// Scratch (device globals — no runtime allocation allowed)
// ---------------------------------------------------------------------------
__device__ __align__(128) float g_xn   [NROWS_ * D_];
__device__ __align__(128) float g_xz   [NROWS_ * 2 * DI_];
__device__ __align__(128) float g_xact [NROWS_ * DI_];
__device__ __align__(128) float g_xssm [NROWS_ * XPROJ_N_];
__device__ __align__(128) float g_gate [NROWS_ * DI_];

// ---------------------------------------------------------------------------
// Small helpers
// ---------------------------------------------------------------------------
__device__ __forceinline__ float siluf(float x) { return x / (1.0f + expf(-x)); }
__device__ __forceinline__ float softplusf(float x) {
    return fmaxf(x, 0.0f) + log1pf(expf(-fabsf(x)));
}

__device__ __forceinline__ uint32_t smem_u32(const void* p) {
    uint32_t a;
    asm("{ .reg .u64 t; cvta.to.shared.u64 t, %1; cvt.u32.u64 %0, t; }"
        : "=r"(a) : "l"(p));
    return a;
}
__device__ __forceinline__ void cp_async16(uint32_t dst, const void* src) {
    asm volatile("cp.async.cg.shared.global [%0], [%1], 16;" :: "r"(dst), "l"(src));
}
__device__ __forceinline__ void cp_commit() {
    asm volatile("cp.async.commit_group;" ::: "memory");
}
template <int N> __device__ __forceinline__ void cp_wait() {
    asm volatile("cp.async.wait_group %0;" :: "n"(N) : "memory");
}
__device__ __forceinline__ uint32_t f2tf32(float x) {
    uint32_t r;
    asm("cvt.rna.tf32.f32 %0, %1;" : "=r"(r) : "f"(x));
    return r;
}
__device__ __forceinline__ void mma_tf32(float* d, const uint32_t* a, const uint32_t* b) {
    asm volatile(
        "mma.sync.aligned.m16n8k8.row.col.f32.tf32.tf32.f32 "
        "{%0,%1,%2,%3}, {%4,%5,%6,%7}, {%8,%9}, {%0,%1,%2,%3};"
        : "+f"(d[0]), "+f"(d[1]), "+f"(d[2]), "+f"(d[3])
        : "r"(a[0]), "r"(a[1]), "r"(a[2]), "r"(a[3]), "r"(b[0]), "r"(b[1]));
}

// ---------------------------------------------------------------------------
// 1) LayerNorm
// ---------------------------------------------------------------------------
__global__ __launch_bounds__(256)
void ln_kernel(const float* __restrict__ x, const float* __restrict__ w,
               const float* __restrict__ b, float* __restrict__ out)
{
    __shared__ float red_s[8], red_q[8];
    const int row = blockIdx.x;
    const float* xr = x + (size_t)row * D_;
    const int c = threadIdx.x * 4;

    float4 v = *(const float4*)(xr + c);
    float s  = v.x + v.y + v.z + v.w;
    float q  = v.x * v.x + v.y * v.y + v.z * v.z + v.w * v.w;
    #pragma unroll
    for (int o = 16; o > 0; o >>= 1) {
        s += __shfl_xor_sync(0xffffffffu, s, o);
        q += __shfl_xor_sync(0xffffffffu, q, o);
    }
    const int warp = threadIdx.x >> 5;
    if ((threadIdx.x & 31) == 0) { red_s[warp] = s; red_q[warp] = q; }
    __syncthreads();
    s = 0.f; q = 0.f;
    #pragma unroll
    for (int i = 0; i < 8; i++) { s += red_s[i]; q += red_q[i]; }

    const float inv = 1.0f / (float)D_;
    const float mu  = s * inv;
    const float var = q * inv - mu * mu;
    const float rs  = rsqrtf(var + 1e-5f);

    float4 wv = *(const float4*)(w + c);
    float4 bv = *(const float4*)(b + c);
    float4 o;
    o.x = (v.x - mu) * rs * wv.x + bv.x;
    o.y = (v.y - mu) * rs * wv.y + bv.y;
    o.z = (v.z - mu) * rs * wv.z + bv.z;
    o.w = (v.w - mu) * rs * wv.w + bv.w;
    *(float4*)(out + (size_t)row * D_ + c) = o;
}

// ---------------------------------------------------------------------------
// 2) tf32 tensor-core GEMM via mma.sync (NT): C[m,n] = sum_k A[m,k]*B[n,k] (+Cadd)
//    BM=128, BN=128, BK=16, 4-stage cp.async pipeline, 256 threads.
//    Warps: 2(m) x 4(n); warp tile 64x32; mma m16n8k8.
// ---------------------------------------------------------------------------
#define BM 128
#define BNT 128
#define BK 16
#define NST 4
#define AST (BK + 4)                 // padded row stride (floats)
#define TILE_F (BM * AST)            // floats per A (or B) tile = 2560
#define STAGE_F (2 * TILE_F)         // 5120 floats per stage
#define GEMM_SMEM (NST * STAGE_F * 4)  // 81920 bytes

__global__ __launch_bounds__(256, 2)
void mma_gemm_kernel(const float* __restrict__ A, const float* __restrict__ B,
                     const float* __restrict__ Cadd, float* __restrict__ C,
                     int N, int K)
{
    extern __shared__ float sm[];
    const uint32_t sm_base = smem_u32(sm);

    const int tid  = threadIdx.x;
    const int lane = tid & 31;
    const int warp = tid >> 5;
    const int gid  = lane >> 2;       // 0..7
    const int tig  = lane & 3;        // 0..3
    const int wm   = (warp & 1) * 64; // warp m offset within block tile
    const int wn   = (warp >> 1) * 32;// warp n offset

    const int m0 = blockIdx.y * BM;
    const int n0 = blockIdx.x * BNT;
    const int nch = K / BK;

    // loader mapping: 2 iterations x 256 threads covers 512 float4 per tile
    const int lrow0 = tid >> 2;          // 0..63
    const int lkq   = (tid & 3) * 4;     // 0,4,8,12

    float acc[4][4][4];
    #pragma unroll
    for (int i = 0; i < 4; i++)
        #pragma unroll
        for (int j = 0; j < 4; j++)
            #pragma unroll
            for (int q = 0; q < 4; q++) acc[i][j][q] = 0.f;

    // ---- prologue: issue NST-1 stages ----
    #pragma unroll
    for (int c = 0; c < NST - 1; c++) {
        const uint32_t sb = sm_base + c * STAGE_F * 4;
        #pragma unroll
        for (int it = 0; it < 2; it++) {
            const int row = lrow0 + it * 64;
            cp_async16(sb + (row * AST + lkq) * 4,
                       A + (size_t)(m0 + row) * K + c * BK + lkq);
            cp_async16(sb + (TILE_F + row * AST + lkq) * 4,
                       B + (size_t)(n0 + row) * K + c * BK + lkq);
        }
        cp_commit();
    }

    // ---- main loop ----
    for (int c = 0; c < nch; c++) {
        cp_wait<NST - 2>();
        __syncthreads();

        // issue stage c+NST-1 (overwrites stage read at iter c-1; safe after barrier)
        const int cn = c + NST - 1;
        if (cn < nch) {
            const uint32_t sb = sm_base + (cn % NST) * STAGE_F * 4;
            #pragma unroll
            for (int it = 0; it < 2; it++) {
                const int row = lrow0 + it * 64;
                cp_async16(sb + (row * AST + lkq) * 4,
                           A + (size_t)(m0 + row) * K + cn * BK + lkq);
                cp_async16(sb + (TILE_F + row * AST + lkq) * 4,
                           B + (size_t)(n0 + row) * K + cn * BK + lkq);
            }
        }
        cp_commit();

        // compute stage c
        const float* As = sm + (c % NST) * STAGE_F;
        const float* Bs = As + TILE_F;

        #pragma unroll
        for (int kk = 0; kk < BK; kk += 8) {
            uint32_t af[4][4], bf[4][2];
            #pragma unroll
            for (int i = 0; i < 4; i++) {
                const float* ap = As + (wm + i * 16 + gid) * AST + kk + tig;
                af[i][0] = f2tf32(ap[0]);
                af[i][1] = f2tf32(ap[8 * AST]);
                af[i][2] = f2tf32(ap[4]);
                af[i][3] = f2tf32(ap[8 * AST + 4]);
            }
            #pragma unroll
            for (int j = 0; j < 4; j++) {
                const float* bp = Bs + (wn + j * 8 + gid) * AST + kk + tig;
                bf[j][0] = f2tf32(bp[0]);
                bf[j][1] = f2tf32(bp[4]);
            }
            #pragma unroll
            for (int i = 0; i < 4; i++)
                #pragma unroll
                for (int j = 0; j < 4; j++)
                    mma_tf32(acc[i][j], af[i], bf[j]);
        }
    }

    // ---- epilogue ----
    #pragma unroll
    for (int i = 0; i < 4; i++) {
        const int row = m0 + wm + i * 16 + gid;
        #pragma unroll
        for (int j = 0; j < 4; j++) {
            const int col = n0 + wn + j * 8 + tig * 2;
            float2 v0 = make_float2(acc[i][j][0], acc[i][j][1]);
            float2 v1 = make_float2(acc[i][j][2], acc[i][j][3]);
            if (Cadd) {
                float2 a0 = *(const float2*)(Cadd + (size_t)row * N + col);
                float2 a1 = *(const float2*)(Cadd + (size_t)(row + 8) * N + col);
                v0.x += a0.x; v0.y += a0.y;
                v1.x += a1.x; v1.y += a1.y;
            }
            *(float2*)(C + (size_t)row * N + col)       = v0;
            *(float2*)(C + (size_t)(row + 8) * N + col) = v1;
        }
    }
}

// ---------------------------------------------------------------------------
// 3) Causal depthwise conv (d_conv=4) + bias + SiLU
// ---------------------------------------------------------------------------
__global__ __launch_bounds__(256)
void conv_silu_kernel(const float* __restrict__ xz, const float* __restrict__ cw,
                      const float* __restrict__ cb, float* __restrict__ xact)
{
    const int idx = blockIdx.x * 256 + threadIdx.x;
    const int b = idx / DI_;
    const int d = idx - b * DI_;

    const float w0 = cw[d * 4 + 0];
    const float w1 = cw[d * 4 + 1];
    const float w2 = cw[d * 4 + 2];
    const float w3 = cw[d * 4 + 3];
    const float bias = cb[d];

    const float* xin = xz + (size_t)b * S_ * (2 * DI_) + d;
    float* out = xact + (size_t)b * S_ * DI_ + d;

    float h0 = 0.f, h1 = 0.f, h2 = 0.f;
    #pragma unroll 4
    for (int s = 0; s < S_; s++) {
        float h3 = xin[(size_t)s * (2 * DI_)];
        float v = bias + w0 * h0 + w1 * h1 + w2 * h2 + w3 * h3;
        out[(size_t)s * DI_] = siluf(v);
        h0 = h1; h1 = h2; h2 = h3;
    }
}

// ---------------------------------------------------------------------------
// 4) x_proj skinny GEMM: [NROWS,2048] @ [65,2048]^T, float4-vectorized LDS
// ---------------------------------------------------------------------------
__global__ __launch_bounds__(256)
void xproj_kernel(const float* __restrict__ A, const float* __restrict__ W,
                  float* __restrict__ out)
{
    __shared__ float As[32][68];
    __shared__ float Ws[65][64];

    const int tid = threadIdx.x;
    const int m0 = blockIdx.x * 32;
    const int r  = tid & 31;
    const int cg = tid >> 5;

    float acc[9];
    #pragma unroll
    for (int j = 0; j < 9; j++) acc[j] = 0.f;

    for (int kt = 0; kt < DI_; kt += 64) {
        __syncthreads();
        for (int i = tid; i < 32 * 16; i += 256) {
            int rr = i >> 4, c4 = (i & 15) * 4;
            float4 v = *(const float4*)(A + (size_t)(m0 + rr) * DI_ + kt + c4);
            *(float4*)&As[rr][c4] = v;
        }
        for (int i = tid; i < 65 * 16; i += 256) {
            int rr = i >> 4, c4 = (i & 15) * 4;
            float4 v = *(const float4*)(W + (size_t)rr * DI_ + kt + c4);
            *(float4*)&Ws[rr][c4] = v;
        }
        __syncthreads();

        #pragma unroll
        for (int k = 0; k < 64; k += 4) {
            float4 a = *(const float4*)&As[r][k];
            #pragma unroll
            for (int j = 0; j < 9; j++) {
                int c = cg + 8 * j;
                if (c < XPROJ_N_) {
                    float4 w = *(const float4*)&Ws[c][k];
                    acc[j] += a.x * w.x + a.y * w.y + a.z * w.z + a.w * w.w;
                }
            }
        }
    }

    #pragma unroll
    for (int j = 0; j < 9; j++) {
        int c = cg + 8 * j;
        if (c < XPROJ_N_) out[(size_t)(m0 + r) * XPROJ_N_ + c] = acc[j];
    }
}

// ---------------------------------------------------------------------------
// 5) SSM scan + gating
// ---------------------------------------------------------------------------
__global__ __launch_bounds__(256)
void scan_kernel(const float* __restrict__ xssm, const float* __restrict__ xact,
                 const float* __restrict__ xz,   const float* __restrict__ dtW,
                 const float* __restrict__ dtb,  const float* __restrict__ eb,
                 const float* __restrict__ es_p, float* __restrict__ gated)
{
    __shared__ float Bc[S_][DS_];
    __shared__ float Cc[S_][DS_];
    __shared__ float dr[S_];
    __shared__ float ebs[S_];

    const int b = blockIdx.x;
    const int d = blockIdx.y * 256 + threadIdx.x;
    const float es = *es_p;

    {
        const float* src = xssm + (size_t)b * S_ * XPROJ_N_;
        for (int i = threadIdx.x; i < S_ * XPROJ_N_; i += 256) {
            int s = i / XPROJ_N_;
            int c = i - s * XPROJ_N_;
            float v = src[i];
            if (c == 0)        dr[s]              = v;
            else if (c <= DS_) Bc[s][c - 1]       = v;
            else               Cc[s][c - 1 - DS_] = v;
        }
        for (int i = threadIdx.x; i < S_; i += 256)
            ebs[i] = eb[(size_t)b * S_ + i];
    }
    __syncthreads();

    const float dw = dtW[d];
    const float db = dtb[d];
    const float* xa_p = xact + (size_t)b * S_ * DI_ + d;
    const float* z_p  = xz   + (size_t)b * S_ * (2 * DI_) + DI_ + d;
    float* out_p      = gated + (size_t)b * S_ * DI_ + d;

    float h[DS_];
    #pragma unroll
    for (int n = 0; n < DS_; n++) h[n] = 0.f;

    for (int s = 0; s < S_; s++) {
        const float xa = xa_p[(size_t)s * DI_];
        const float zz = z_p[(size_t)s * (2 * DI_)];
        float delta = softplusf(dr[s] * dw + db);
        delta = fmaxf(delta + es * ebs[s], 1e-4f);
        const float e = expf(-delta);
        float y = 0.f;
        #pragma unroll
        for (int n = 0; n < DS_; n++) {
            float hn = h[n] * e + Bc[s][n] * xa;
            hn = fminf(fmaxf(hn, -100.0f), 100.0f);
            h[n] = hn;
            y += hn * Cc[s][n];
        }
        out_p[(size_t)s * DI_] = y * siluf(zz);
    }
}

// ---------------------------------------------------------------------------
// launch
// ---------------------------------------------------------------------------
extern "C" void kernel_launch(void* const* d_in, const int* in_sizes, int n_in,
                              void* d_out, int out_size)
{
    const float* x      = (const float*)d_in[0];
    const float* eb     = (const float*)d_in[1];
    const float* norm_w = (const float*)d_in[2];
    const float* norm_b = (const float*)d_in[3];
    const float* inW    = (const float*)d_in[4];
    const float* convw  = (const float*)d_in[5];
    const float* convb  = (const float*)d_in[6];
    const float* xpW    = (const float*)d_in[7];
    const float* dtW    = (const float*)d_in[8];
    const float* dtb    = (const float*)d_in[9];
    const float* outW   = (const float*)d_in[10];
    const float* es     = (const float*)d_in[11];
    float* out = (float*)d_out;

    float *xn, *xz, *xact, *xssm, *gate;
    cudaGetSymbolAddress((void**)&xn,   g_xn);
    cudaGetSymbolAddress((void**)&xz,   g_xz);
    cudaGetSymbolAddress((void**)&xact, g_xact);
    cudaGetSymbolAddress((void**)&xssm, g_xssm);
    cudaGetSymbolAddress((void**)&gate, g_gate);

    cudaFuncSetAttribute(mma_gemm_kernel,
                         cudaFuncAttributeMaxDynamicSharedMemorySize, GEMM_SMEM);

    // 1) LayerNorm
    ln_kernel<<<NROWS_, 256>>>(x, norm_w, norm_b, xn);

    // 2) in_proj GEMM (tf32 mma.sync): [25600,1024] x [4096,1024]^T
    {
        dim3 grid((2 * DI_) / BNT, NROWS_ / BM);
        mma_gemm_kernel<<<grid, 256, GEMM_SMEM>>>(xn, inW, nullptr, xz, 2 * DI_, D_);
    }

    // 3) causal depthwise conv + SiLU
    conv_silu_kernel<<<(BN_ * DI_) / 256, 256>>>(xz, convw, convb, xact);

    // 4) x_proj skinny GEMM
    xproj_kernel<<<NROWS_ / 32, 256>>>(xact, xpW, xssm);

    // 5) SSM scan + gating
    {
        dim3 grid(BN_, DI_ / 256);
        scan_kernel<<<grid, 256>>>(xssm, xact, xz, dtW, dtb, eb, es, gate);
    }

    // 6) out GEMM + residual (tf32 mma.sync): [25600,2048] x [1024,2048]^T + x
    {
        dim3 grid(D_ / BNT, NROWS_ / BM);
        mma_gemm_kernel<<<grid, 256, GEMM_SMEM>>>(gate, outW, x, out, D_, DI_);
    }
}

// round 4
// speedup vs baseline: 2.7069x; 1.1310x over previous
#include <cuda_runtime.h>
#include <math.h>
#include <cstdint>

// ---------------------------------------------------------------------------
// Problem dims
// ---------------------------------------------------------------------------
#define BN_      200
#define S_       128
#define D_       1024
#define DI_      2048
#define DS_      32
#define NROWS_   (BN_ * S_)          // 25600
#define XPROJ_N_ (2 * DS_ + 1)       // 65

// ---------------------------------------------------------------------------
// Scratch (device globals — no runtime allocation allowed)
// ---------------------------------------------------------------------------
__device__ __align__(128) float g_xn   [NROWS_ * D_];
__device__ __align__(128) float g_xact [NROWS_ * DI_];     // conv+silu output
__device__ __align__(128) float g_zs   [NROWS_ * DI_];     // silu(z)
__device__ __align__(128) float g_xssm [NROWS_ * XPROJ_N_];
__device__ __align__(128) float g_gate [NROWS_ * DI_];     // y * silu(z)

// ---------------------------------------------------------------------------
// Small helpers
// ---------------------------------------------------------------------------
__device__ __forceinline__ float siluf(float x) { return x / (1.0f + expf(-x)); }
__device__ __forceinline__ float softplusf(float x) {
    return fmaxf(x, 0.0f) + log1pf(expf(-fabsf(x)));
}

__device__ __forceinline__ uint32_t smem_u32(const void* p) {
    uint32_t a;
    asm("{ .reg .u64 t; cvta.to.shared.u64 t, %1; cvt.u32.u64 %0, t; }"
        : "=r"(a) : "l"(p));
    return a;
}
__device__ __forceinline__ void cp_async16(uint32_t dst, const void* src) {
    asm volatile("cp.async.cg.shared.global [%0], [%1], 16;" :: "r"(dst), "l"(src));
}
__device__ __forceinline__ void cp_commit() {
    asm volatile("cp.async.commit_group;" ::: "memory");
}
template <int N> __device__ __forceinline__ void cp_wait() {
    asm volatile("cp.async.wait_group %0;" :: "n"(N) : "memory");
}
__device__ __forceinline__ uint32_t f2tf32(float x) {
    uint32_t r;
    asm("cvt.rna.tf32.f32 %0, %1;" : "=r"(r) : "f"(x));
    return r;
}
__device__ __forceinline__ void mma_tf32(float* d, const uint32_t* a, const uint32_t* b) {
    asm volatile(
        "mma.sync.aligned.m16n8k8.row.col.f32.tf32.tf32.f32 "
        "{%0,%1,%2,%3}, {%4,%5,%6,%7}, {%8,%9}, {%0,%1,%2,%3};"
        : "+f"(d[0]), "+f"(d[1]), "+f"(d[2]), "+f"(d[3])
        : "r"(a[0]), "r"(a[1]), "r"(a[2]), "r"(a[3]), "r"(b[0]), "r"(b[1]));
}

// ---------------------------------------------------------------------------
// 1) LayerNorm
// ---------------------------------------------------------------------------
__global__ __launch_bounds__(256)
void ln_kernel(const float* __restrict__ x, const float* __restrict__ w,
               const float* __restrict__ b, float* __restrict__ out)
{
    __shared__ float red_s[8], red_q[8];
    const int row = blockIdx.x;
    const float* xr = x + (size_t)row * D_;
    const int c = threadIdx.x * 4;

    float4 v = *(const float4*)(xr + c);
    float s  = v.x + v.y + v.z + v.w;
    float q  = v.x * v.x + v.y * v.y + v.z * v.z + v.w * v.w;
    #pragma unroll
    for (int o = 16; o > 0; o >>= 1) {
        s += __shfl_xor_sync(0xffffffffu, s, o);
        q += __shfl_xor_sync(0xffffffffu, q, o);
    }
    const int warp = threadIdx.x >> 5;
    if ((threadIdx.x & 31) == 0) { red_s[warp] = s; red_q[warp] = q; }
    __syncthreads();
    s = 0.f; q = 0.f;
    #pragma unroll
    for (int i = 0; i < 8; i++) { s += red_s[i]; q += red_q[i]; }

    const float inv = 1.0f / (float)D_;
    const float mu  = s * inv;
    const float var = q * inv - mu * mu;
    const float rs  = rsqrtf(var + 1e-5f);

    float4 wv = *(const float4*)(w + c);
    float4 bv = *(const float4*)(b + c);
    float4 o;
    o.x = (v.x - mu) * rs * wv.x + bv.x;
    o.y = (v.y - mu) * rs * wv.y + bv.y;
    o.z = (v.z - mu) * rs * wv.z + bv.z;
    o.w = (v.w - mu) * rs * wv.w + bv.w;
    *(float4*)(out + (size_t)row * D_ + c) = o;
}

// ---------------------------------------------------------------------------
// 2) tf32 tensor-core GEMM via mma.sync (NT): acc[m,n] = sum_k A[m,k]*B[n,k]
//    BM=128, BN=128, BK=16, 4-stage cp.async, 256 threads, warp tile 64x32.
//    FUSED=false: C = acc (+Cadd)                      [out GEMM]
//    FUSED=true : n<2048 -> conv(s)+silu -> xact       [in_proj GEMM]
//                 n>=2048 -> silu(acc)   -> zs
// ---------------------------------------------------------------------------
#define BM 128
#define BNT 128
#define BK 16
#define NST 4
#define AST (BK + 4)
#define TILE_F (BM * AST)            // 2560
#define STAGE_F (2 * TILE_F)         // 5120
#define GEMM_SMEM (NST * STAGE_F * 4)  // 81920 bytes (also >= 128*132*4 stage)

template <bool FUSED>
__global__ __launch_bounds__(256, 2)
void mma_gemm_kernel(const float* __restrict__ A, const float* __restrict__ B,
                     const float* __restrict__ Cadd, float* __restrict__ C,
                     float* __restrict__ zs, const float* __restrict__ cw,
                     const float* __restrict__ cb, int N, int K)
{
    extern __shared__ float sm[];
    const uint32_t sm_base = smem_u32(sm);

    const int tid  = threadIdx.x;
    const int lane = tid & 31;
    const int warp = tid >> 5;
    const int gid  = lane >> 2;
    const int tig  = lane & 3;
    const int wm   = (warp & 1) * 64;
    const int wn   = (warp >> 1) * 32;

    const int m0 = blockIdx.y * BM;
    const int n0 = blockIdx.x * BNT;
    const int nch = K / BK;

    const int lrow0 = tid >> 2;
    const int lkq   = (tid & 3) * 4;

    float acc[4][4][4];
    #pragma unroll
    for (int i = 0; i < 4; i++)
        #pragma unroll
        for (int j = 0; j < 4; j++)
            #pragma unroll
            for (int q = 0; q < 4; q++) acc[i][j][q] = 0.f;

    #pragma unroll
    for (int c = 0; c < NST - 1; c++) {
        const uint32_t sb = sm_base + c * STAGE_F * 4;
        #pragma unroll
        for (int it = 0; it < 2; it++) {
            const int row = lrow0 + it * 64;
            cp_async16(sb + (row * AST + lkq) * 4,
                       A + (size_t)(m0 + row) * K + c * BK + lkq);
            cp_async16(sb + (TILE_F + row * AST + lkq) * 4,
                       B + (size_t)(n0 + row) * K + c * BK + lkq);
        }
        cp_commit();
    }

    for (int c = 0; c < nch; c++) {
        cp_wait<NST - 2>();
        __syncthreads();

        const int cn = c + NST - 1;
        if (cn < nch) {
            const uint32_t sb = sm_base + (cn % NST) * STAGE_F * 4;
            #pragma unroll
            for (int it = 0; it < 2; it++) {
                const int row = lrow0 + it * 64;
                cp_async16(sb + (row * AST + lkq) * 4,
                           A + (size_t)(m0 + row) * K + cn * BK + lkq);
                cp_async16(sb + (TILE_F + row * AST + lkq) * 4,
                           B + (size_t)(n0 + row) * K + cn * BK + lkq);
            }
        }
        cp_commit();

        const float* As = sm + (c % NST) * STAGE_F;
        const float* Bs = As + TILE_F;

        #pragma unroll
        for (int kk = 0; kk < BK; kk += 8) {
            uint32_t af[4][4], bf[4][2];
            #pragma unroll
            for (int i = 0; i < 4; i++) {
                const float* ap = As + (wm + i * 16 + gid) * AST + kk + tig;
                af[i][0] = f2tf32(ap[0]);
                af[i][1] = f2tf32(ap[8 * AST]);
                af[i][2] = f2tf32(ap[4]);
                af[i][3] = f2tf32(ap[8 * AST + 4]);
            }
            #pragma unroll
            for (int j = 0; j < 4; j++) {
                const float* bp = Bs + (wn + j * 8 + gid) * AST + kk + tig;
                bf[j][0] = f2tf32(bp[0]);
                bf[j][1] = f2tf32(bp[4]);
            }
            #pragma unroll
            for (int i = 0; i < 4; i++)
                #pragma unroll
                for (int j = 0; j < 4; j++)
                    mma_tf32(acc[i][j], af[i], bf[j]);
        }
    }

    if (!FUSED) {
        // ---- plain epilogue (+ residual) ----
        #pragma unroll
        for (int i = 0; i < 4; i++) {
            const int row = m0 + wm + i * 16 + gid;
            #pragma unroll
            for (int j = 0; j < 4; j++) {
                const int col = n0 + wn + j * 8 + tig * 2;
                float2 v0 = make_float2(acc[i][j][0], acc[i][j][1]);
                float2 v1 = make_float2(acc[i][j][2], acc[i][j][3]);
                if (Cadd) {
                    float2 a0 = *(const float2*)(Cadd + (size_t)row * N + col);
                    float2 a1 = *(const float2*)(Cadd + (size_t)(row + 8) * N + col);
                    v0.x += a0.x; v0.y += a0.y;
                    v1.x += a1.x; v1.y += a1.y;
                }
                *(float2*)(C + (size_t)row * N + col)       = v0;
                *(float2*)(C + (size_t)(row + 8) * N + col) = v1;
            }
        }
    } else if (n0 >= DI_) {
        // ---- z half: silu -> zs ----
        const int zc0 = n0 - DI_;
        #pragma unroll
        for (int i = 0; i < 4; i++) {
            const int row = m0 + wm + i * 16 + gid;
            #pragma unroll
            for (int j = 0; j < 4; j++) {
                const int col = zc0 + wn + j * 8 + tig * 2;
                float2 v0 = make_float2(siluf(acc[i][j][0]), siluf(acc[i][j][1]));
                float2 v1 = make_float2(siluf(acc[i][j][2]), siluf(acc[i][j][3]));
                *(float2*)(zs + (size_t)row * DI_ + col)       = v0;
                *(float2*)(zs + (size_t)(row + 8) * DI_ + col) = v1;
            }
        }
    } else {
        // ---- x half: stage tile, causal conv along s (m within tile), silu ----
        // tile rows are exactly s=0..127 of batch b = blockIdx.y (BM == S)
        __syncthreads();   // smem stages no longer needed
        float* stage = sm;                         // [128][132]
        #pragma unroll
        for (int i = 0; i < 4; i++) {
            const int r0 = wm + i * 16 + gid;
            #pragma unroll
            for (int j = 0; j < 4; j++) {
                const int cc = wn + j * 8 + tig * 2;
                *(float2*)&stage[(r0)     * 132 + cc] = make_float2(acc[i][j][0], acc[i][j][1]);
                *(float2*)&stage[(r0 + 8) * 132 + cc] = make_float2(acc[i][j][2], acc[i][j][3]);
            }
        }
        __syncthreads();

        const int dl = tid & 127;                  // d within tile
        const int sh = tid >> 7;                   // 0/1 : s-half
        const int d  = n0 + dl;
        const float4 w4 = *(const float4*)(cw + (size_t)d * 4);
        const float bias = cb[d];

        const int s0 = sh * 64;
        float h0 = (s0 >= 3) ? stage[(s0 - 3) * 132 + dl] : 0.f;
        float h1 = (s0 >= 2) ? stage[(s0 - 2) * 132 + dl] : 0.f;
        float h2 = (s0 >= 1) ? stage[(s0 - 1) * 132 + dl] : 0.f;

        float* outp = g_xact + (size_t)(m0 + s0) * DI_ + d;
        #pragma unroll 4
        for (int s = 0; s < 64; s++) {
            float h3 = stage[(s0 + s) * 132 + dl];
            float v = bias + w4.x * h0 + w4.y * h1 + w4.z * h2 + w4.w * h3;
            outp[(size_t)s * DI_] = siluf(v);
            h0 = h1; h1 = h2; h2 = h3;
        }
    }
}

// ---------------------------------------------------------------------------
// 3) x_proj GEMM on tensor cores: [NROWS,2048] @ [65,2048]^T -> [NROWS,65]
//    BM=64, N=65 (9 n8-tiles, W rows 65..71 zero), BK=32, 3-stage cp.async.
// ---------------------------------------------------------------------------
#define XBM 64
#define XBK 32
#define XST 36
#define XNST 3
#define XA_F (XBM * XST)             // 2304
#define XB_F (72 * XST)              // 2592
#define XSTAGE_F (XA_F + XB_F)       // 4896
#define XPROJ_SMEM (XNST * XSTAGE_F * 4)  // 58752 bytes

__global__ __launch_bounds__(128, 4)
void xproj_mma_kernel(const float* __restrict__ A, const float* __restrict__ W,
                      float* __restrict__ out)
{
    extern __shared__ float sm[];
    const uint32_t sm_base = smem_u32(sm);

    const int tid  = threadIdx.x;
    const int lane = tid & 31;
    const int warp = tid >> 5;        // 0..3, warp m-tile = warp*16
    const int gid  = lane >> 2;
    const int tig  = lane & 3;
    const int m0   = blockIdx.x * XBM;

    // zero the pad rows (65..71) of all W stages once
    for (int i = tid; i < XNST * 7 * XST; i += 128) {
        const int st  = i / (7 * XST);
        const int rem = i - st * (7 * XST);
        sm[st * XSTAGE_F + XA_F + 65 * XST + rem] = 0.f;
    }

    const int nch = DI_ / XBK;        // 64

    float acc[9][4];
    #pragma unroll
    for (int j = 0; j < 9; j++)
        #pragma unroll
        for (int q = 0; q < 4; q++) acc[j][q] = 0.f;

    // prologue: 2 stages
    #pragma unroll
    for (int c = 0; c < XNST - 1; c++) {
        const uint32_t sb = sm_base + c * XSTAGE_F * 4;
        #pragma unroll
        for (int it = 0; it < 4; it++) {
            const int idx = it * 128 + tid;
            const int row = idx >> 3, kq = (idx & 7) * 4;
            cp_async16(sb + (row * XST + kq) * 4,
                       A + (size_t)(m0 + row) * DI_ + c * XBK + kq);
        }
        #pragma unroll
        for (int it = 0; it < 5; it++) {
            const int idx = it * 128 + tid;
            if (idx < 520) {
                const int row = idx >> 3, kq = (idx & 7) * 4;
                cp_async16(sb + (XA_F + row * XST + kq) * 4,
                           W + (size_t)row * DI_ + c * XBK + kq);
            }
        }
        cp_commit();
    }

    for (int c = 0; c < nch; c++) {
        cp_wait<XNST - 2>();
        __syncthreads();

        const int cn = c + XNST - 1;
        if (cn < nch) {
            const uint32_t sb = sm_base + (cn % XNST) * XSTAGE_F * 4;
            #pragma unroll
            for (int it = 0; it < 4; it++) {
                const int idx = it * 128 + tid;
                const int row = idx >> 3, kq = (idx & 7) * 4;
                cp_async16(sb + (row * XST + kq) * 4,
                           A + (size_t)(m0 + row) * DI_ + cn * XBK + kq);
            }
            #pragma unroll
            for (int it = 0; it < 5; it++) {
                const int idx = it * 128 + tid;
                if (idx < 520) {
                    const int row = idx >> 3, kq = (idx & 7) * 4;
                    cp_async16(sb + (XA_F + row * XST + kq) * 4,
                               W + (size_t)row * DI_ + cn * XBK + kq);
                }
            }
        }
        cp_commit();

        const float* As = sm + (c % XNST) * XSTAGE_F;
        const float* Ws = As + XA_F;

        #pragma unroll
        for (int kk = 0; kk < XBK; kk += 8) {
            uint32_t af[4];
            const float* ap = As + (warp * 16 + gid) * XST + kk + tig;
            af[0] = f2tf32(ap[0]);
            af[1] = f2tf32(ap[8 * XST]);
            af[2] = f2tf32(ap[4]);
            af[3] = f2tf32(ap[8 * XST + 4]);
            #pragma unroll
            for (int j = 0; j < 9; j++) {
                uint32_t bf[2];
                const float* bp = Ws + (j * 8 + gid) * XST + kk + tig;
                bf[0] = f2tf32(bp[0]);
                bf[1] = f2tf32(bp[4]);
                mma_tf32(acc[j], af, bf);
            }
        }
    }

    // epilogue with column guards (N = 65)
    const int row0 = m0 + warp * 16 + gid;
    #pragma unroll
    for (int j = 0; j < 9; j++) {
        const int col = j * 8 + tig * 2;
        if (col < XPROJ_N_)     out[(size_t)row0 * XPROJ_N_ + col]           = acc[j][0];
        if (col + 1 < XPROJ_N_) out[(size_t)row0 * XPROJ_N_ + col + 1]       = acc[j][1];
        if (col < XPROJ_N_)     out[(size_t)(row0 + 8) * XPROJ_N_ + col]     = acc[j][2];
        if (col + 1 < XPROJ_N_) out[(size_t)(row0 + 8) * XPROJ_N_ + col + 1] = acc[j][3];
    }
}

// ---------------------------------------------------------------------------
// 4) SSM scan + gating (z pre-silu'd in GEMM1 epilogue)
// ---------------------------------------------------------------------------
__global__ __launch_bounds__(256)
void scan_kernel(const float* __restrict__ xssm, const float* __restrict__ xact,
                 const float* __restrict__ zs,   const float* __restrict__ dtW,
                 const float* __restrict__ dtb,  const float* __restrict__ eb,
                 const float* __restrict__ es_p, float* __restrict__ gated)
{
    __shared__ float Bc[S_][DS_];
    __shared__ float Cc[S_][DS_];
    __shared__ float dr[S_];
    __shared__ float ebs[S_];

    const int b = blockIdx.x;
    const int d = blockIdx.y * 256 + threadIdx.x;
    const float es = *es_p;

    {
        const float* src = xssm + (size_t)b * S_ * XPROJ_N_;
        for (int i = threadIdx.x; i < S_ * XPROJ_N_; i += 256) {
            int s = i / XPROJ_N_;
            int c = i - s * XPROJ_N_;
            float v = src[i];
            if (c == 0)        dr[s]              = v;
            else if (c <= DS_) Bc[s][c - 1]       = v;
            else               Cc[s][c - 1 - DS_] = v;
        }
        for (int i = threadIdx.x; i < S_; i += 256)
            ebs[i] = eb[(size_t)b * S_ + i];
    }
    __syncthreads();

    const float dw = dtW[d];
    const float db = dtb[d];
    const float* xa_p = xact + (size_t)b * S_ * DI_ + d;
    const float* z_p  = zs   + (size_t)b * S_ * DI_ + d;
    float* out_p      = gated + (size_t)b * S_ * DI_ + d;

    float h[DS_];
    #pragma unroll
    for (int n = 0; n < DS_; n++) h[n] = 0.f;

    for (int s = 0; s < S_; s++) {
        const float xa = xa_p[(size_t)s * DI_];
        const float zz = z_p[(size_t)s * DI_];
        float delta = softplusf(dr[s] * dw + db);
        delta = fmaxf(delta + es * ebs[s], 1e-4f);
        const float e = expf(-delta);
        float y = 0.f;
        #pragma unroll
        for (int n = 0; n < DS_; n++) {
            float hn = h[n] * e + Bc[s][n] * xa;
            hn = fminf(fmaxf(hn, -100.0f), 100.0f);
            h[n] = hn;
            y += hn * Cc[s][n];
        }
        out_p[(size_t)s * DI_] = y * zz;
    }
}

// ---------------------------------------------------------------------------
// launch
// ---------------------------------------------------------------------------
extern "C" void kernel_launch(void* const* d_in, const int* in_sizes, int n_in,
                              void* d_out, int out_size)
{
    const float* x      = (const float*)d_in[0];
    const float* eb     = (const float*)d_in[1];
    const float* norm_w = (const float*)d_in[2];
    const float* norm_b = (const float*)d_in[3];
    const float* inW    = (const float*)d_in[4];
    const float* convw  = (const float*)d_in[5];
    const float* convb  = (const float*)d_in[6];
    const float* xpW    = (const float*)d_in[7];
    const float* dtW    = (const float*)d_in[8];
    const float* dtb    = (const float*)d_in[9];
    const float* outW   = (const float*)d_in[10];
    const float* es     = (const float*)d_in[11];
    float* out = (float*)d_out;

    float *xn, *xact, *zs, *xssm, *gate;
    cudaGetSymbolAddress((void**)&xn,   g_xn);
    cudaGetSymbolAddress((void**)&xact, g_xact);
    cudaGetSymbolAddress((void**)&zs,   g_zs);
    cudaGetSymbolAddress((void**)&xssm, g_xssm);
    cudaGetSymbolAddress((void**)&gate, g_gate);

    cudaFuncSetAttribute(mma_gemm_kernel<true>,
                         cudaFuncAttributeMaxDynamicSharedMemorySize, GEMM_SMEM);
    cudaFuncSetAttribute(mma_gemm_kernel<false>,
                         cudaFuncAttributeMaxDynamicSharedMemorySize, GEMM_SMEM);
    cudaFuncSetAttribute(xproj_mma_kernel,
                         cudaFuncAttributeMaxDynamicSharedMemorySize, XPROJ_SMEM);

    // 1) LayerNorm
    ln_kernel<<<NROWS_, 256>>>(x, norm_w, norm_b, xn);

    // 2) in_proj GEMM + fused conv/silu epilogue -> xact, zs
    {
        dim3 grid((2 * DI_) / BNT, NROWS_ / BM);
        mma_gemm_kernel<true><<<grid, 256, GEMM_SMEM>>>(
            xn, inW, nullptr, nullptr, zs, convw, convb, 2 * DI_, D_);
    }

    // 3) x_proj GEMM (tensor cores) -> [NROWS, 65]
    xproj_mma_kernel<<<NROWS_ / XBM, 128, XPROJ_SMEM>>>(xact, xpW, xssm);

    // 4) SSM scan + gating
    {
        dim3 grid(BN_, DI_ / 256);
        scan_kernel<<<grid, 256>>>(xssm, xact, zs, dtW, dtb, eb, es, gate);
    }

    // 5) out GEMM + residual
    {
        dim3 grid(D_ / BNT, NROWS_ / BM);
        mma_gemm_kernel<false><<<grid, 256, GEMM_SMEM>>>(
            gate, outW, x, out, nullptr, nullptr, nullptr, D_, DI_);
    }
}